// round 15
// baseline (speedup 1.0000x reference)
#include <cuda_runtime.h>
#include <cstdint>

// Wilson-Cowan rate recurrence, B=8, T=4096, N=1024.
//   Phi(x) = M*x/(x^2+sigma^2) * relu(x+th)
//   nu_{t+1} = (1-dt/tau)*nu_t + (dt/tau)*Phi(E_t - r*nu_t)
//
// Parallel-in-time: CHUNKS=8, WARM=96 (seam error measured 2.69e-4, 3.7x
// under the 1e-3 gate). Two channels per thread (ILP=2) -- best in-kernel
// config (ncu 44.9us).
//
// R15 single change: output stores switch .cs -> .wt (write-through).
// Steady-state replay is bound by sustained mixed r/w DRAM throughput;
// with .cs, ~45-80MB of dirty output lines drain out of L2 INTO THE NEXT
// REPLAY's read phase (harness-ncu gap grew 3.8 -> 7.5us as the kernel got
// faster). Write-through moves those bytes during the kernel, where DRAM
// is only ~65% active, instead of colliding with the next period's reads.

#define CW_B 8
#define CW_T 4096
#define CW_N 1024
#define CW_DT 0.1f

#define CHUNKS 8
#define CW_L   (CW_T / CHUNKS)   // 512 output steps per chunk
#define WARM   96                // warm-up steps (multiple of K_TILE)

#define K_TILE 32                // time steps per tile
#define STAGES 3                 // pipeline depth
#define NTHREADS 64              // threads per CTA (2 warps)
#define CTA_CH 128               // channels per CTA (2 per thread)
#define WARPS  2
#define CH_PER_WARP 64           // channels per warp
// warp-tile: 32 steps x 64 ch x 4B = 8KB = 512 float4; 16 cp.async per lane
#define F4_PER_WARP_TILE (K_TILE * CH_PER_WARP / 4)
#define PASSES (F4_PER_WARP_TILE / 32)       // 16

__device__ __forceinline__ uint64_t mk_evict_last_policy() {
    uint64_t pol;
    asm volatile("createpolicy.fractional.L2::evict_last.b64 %0, 1.0;\n"
                 : "=l"(pol));
    return pol;
}
__device__ __forceinline__ void cp_async16_el(void* smem_dst, const void* gmem_src,
                                              uint64_t pol) {
    unsigned saddr = (unsigned)__cvta_generic_to_shared(smem_dst);
    asm volatile("cp.async.cg.shared.global.L2::cache_hint [%0], [%1], 16, %2;\n"
                 :: "r"(saddr), "l"(gmem_src), "l"(pol));
}
__device__ __forceinline__ void cp_commit() {
    asm volatile("cp.async.commit_group;\n" ::: "memory");
}
template <int Npend>
__device__ __forceinline__ void cp_wait() {
    asm volatile("cp.async.wait_group %0;\n" :: "n"(Npend) : "memory");
}

__global__ __launch_bounds__(NTHREADS, 1)
void cw_recurrence_kernel(const float* __restrict__ E,
                          const float* __restrict__ r,
                          const float* __restrict__ tau_nu,
                          const float* __restrict__ M,
                          const float* __restrict__ sigma,
                          const float* __restrict__ th,
                          float* __restrict__ out)
{
    // [stage][warp][512 float4]  (each warp owns an 8KB tile slice) = 48KB
    __shared__ float4 sbuf[STAGES][WARPS][F4_PER_WARP_TILE];

    const int tid   = threadIdx.x;
    const int w     = tid >> 5;
    const int lane  = tid & 31;

    const int nCtaPerCh = (CW_B * CW_N) / CTA_CH;        // 64
    const int chunk = blockIdx.x / nCtaPerCh;            // 0..CHUNKS-1
    const int cta   = blockIdx.x % nCtaPerCh;

    const int ch0 = cta * CTA_CH;                        // first channel of CTA
    const int b   = ch0 >> 10;                           // batch (uniform per CTA)
    const int nw0 = (ch0 & (CW_N - 1)) + CH_PER_WARP * w; // warp's first channel
    const int nn  = nw0 + 2 * lane;                      // this thread's channel pair

    // Per-channel constants for both channels (float2, off the chain)
    const float2 rr2  = *(const float2*)(r + nn);
    const float2 tau2 = *(const float2*)(tau_nu + nn);
    const float2 M2   = *(const float2*)(M + nn);
    const float2 sg2  = *(const float2*)(sigma + nn);
    const float2 th2  = *(const float2*)(th + nn);

    const float coef0 = CW_DT / tau2.x,  coef1 = CW_DT / tau2.y;
    const float a0 = 1.0f - coef0,       a1 = 1.0f - coef1;
    const float cM0 = coef0 * M2.x,      cM1 = coef1 * M2.y;
    const float s20 = sg2.x * sg2.x,     s21 = sg2.y * sg2.y;

    const int warm    = (chunk == 0) ? 0 : WARM;
    const int t0      = chunk * CW_L - warm;             // first integrated step
    const int nsteps  = CW_L + warm;
    const int NT      = nsteps / K_TILE;                 // tiles this chunk
    const int warm_nt = warm / K_TILE;                   // tiles with no store

    const float* eWarp = E + ((size_t)b * CW_T + t0) * CW_N + nw0;
    float2*      oPtr  = (float2*)(out + ((size_t)b * CW_T + t0) * CW_N + nn);

    const uint64_t pol = mk_evict_last_policy();

    // per-warp async tile load: rows [tile*K, tile*K+K), channels [nw0, nw0+64)
    auto load_tile = [&](int tile, int stage) {
        const float* src = eWarp + (size_t)tile * K_TILE * CW_N;
        #pragma unroll
        for (int p = 0; p < PASSES; ++p) {
            int idx = p * 32 + lane;         // 0..511
            int j   = idx >> 4;              // time row (16 float4 per row)
            int c4  = idx & 15;              // float4 column
            cp_async16_el(&sbuf[stage][w][j * 16 + c4],
                          src + (size_t)j * CW_N + (c4 << 2), pol);
        }
    };

    #pragma unroll
    for (int s0 = 0; s0 < STAGES; ++s0) {
        load_tile(s0, s0);
        cp_commit();
    }

    float nu0 = 0.0f, nu1 = 0.0f;

    for (int tile = 0; tile < NT; ++tile) {
        cp_wait<STAGES - 1>();               // this tile's group complete (per-thread)

        const int stage = tile % STAGES;
        const float2* sf2 = (const float2*)&sbuf[stage][w][0];
        float2* op = oPtr + (size_t)tile * K_TILE * (CW_N / 2);
        const bool do_store = (tile >= warm_nt);

        #pragma unroll
        for (int j = 0; j < K_TILE; ++j) {
            const float2 e2 = sf2[j * 32 + lane];  // channels 2*lane, 2*lane+1

            // two independent chains (ILP=2): u -> d -> rcp -> fma
            const float u0 = fmaf(-rr2.x, nu0, e2.x);
            const float u1 = fmaf(-rr2.y, nu1, e2.y);
            const float d0 = fmaf(u0, u0, s20);
            const float d1 = fmaf(u1, u1, s21);
            float ri0, ri1;
            asm("rcp.approx.f32 %0, %1;" : "=f"(ri0) : "f"(d0));
            asm("rcp.approx.f32 %0, %1;" : "=f"(ri1) : "f"(d1));

            // off-chain, overlaps the rcps
            const float an0 = a0 * nu0;
            const float an1 = a1 * nu1;
            const float rl0 = fmaxf(u0 + th2.x, 0.0f);
            const float rl1 = fmaxf(u1 + th2.y, 0.0f);
            const float p0  = cM0 * u0 * rl0;
            const float p1  = cM1 * u1 * rl1;

            nu0 = fmaf(p0, ri0, an0);
            nu1 = fmaf(p1, ri1, an1);
            if (do_store) {
                float2 o; o.x = nu0; o.y = nu1;
                __stwt(&op[(size_t)j * (CW_N / 2)], o);  // ST.E.WT: write-through,
                                                         // no dirty L2 at kernel end
            }
        }

        const int nxt = tile + STAGES;
        if (nxt < NT) load_tile(nxt, stage); // warp-private: no __syncthreads needed
        cp_commit();                         // keep group count consistent
    }
}

extern "C" void kernel_launch(void* const* d_in, const int* in_sizes, int n_in,
                              void* d_out, int out_size)
{
    const float* E      = (const float*)d_in[0];
    const float* r      = (const float*)d_in[1];
    const float* tau_nu = (const float*)d_in[2];
    const float* M      = (const float*)d_in[3];
    const float* sigma  = (const float*)d_in[4];
    const float* th     = (const float*)d_in[5];
    float* out = (float*)d_out;

    // 64 CTAs per chunk x 8 chunks = 512 CTAs, 64 threads each (1024 warps)
    cw_recurrence_kernel<<<((CW_B * CW_N) / CTA_CH) * CHUNKS, NTHREADS>>>(
        E, r, tau_nu, M, sigma, th, out);
}

// round 16
// speedup vs baseline: 1.0393x; 1.0393x over previous
#include <cuda_runtime.h>
#include <cstdint>

// Wilson-Cowan rate recurrence, B=8, T=4096, N=1024.
//   Phi(x) = M*x/(x^2+sigma^2) * relu(x+th)
//   nu_{t+1} = (1-dt/tau)*nu_t + (dt/tau)*Phi(E_t - r*nu_t)
//
// Parallel-in-time: CHUNKS=4, WARM=96 (validated rel_err 1.75e-4).
//
// Steady-state replay is pinned at ~5.2 TB/s sustained DRAM throughput
// (harness == traffic/5.2TB/s within 2% across 6 configs), so the only
// lever is bytes. The 9MB of E rows at chunk seams ([cL-96, cL), c=1..3)
// are read TWICE per launch ~43us apart (chunk c warm-up early, chunk c-1
// tail late). R16: pin exactly those tiles with L2::evict_last (7% of L2 --
// cannot self-thrash, unlike R8/R9's 96-128MB attempts); all other E loads
// evict_first; outputs .cs. Second read hits L2 -> DRAM reads drop to the
// 128MB minimum.

#define CW_B 8
#define CW_T 4096
#define CW_N 1024
#define CW_DT 0.1f

#define CHUNKS 4
#define CW_L   (CW_T / CHUNKS)   // 1024 output steps per chunk
#define WARM   96                // warm-up steps (multiple of K_TILE)

#define K_TILE 32                // time steps per tile
#define STAGES 3                 // pipeline depth
#define CTA_CH 64                // channels per CTA (2 warps)
#define WARPS  (CTA_CH / 32)
#define F4_PER_WARP_TILE (K_TILE * 32 / 4)   // 256 float4 per warp-tile
#define PASSES (F4_PER_WARP_TILE / 32)       // 8 cp.async per lane per tile

__device__ __forceinline__ uint64_t mk_evict_last_policy() {
    uint64_t pol;
    asm volatile("createpolicy.fractional.L2::evict_last.b64 %0, 1.0;\n"
                 : "=l"(pol));
    return pol;
}
__device__ __forceinline__ uint64_t mk_evict_first_policy() {
    uint64_t pol;
    asm volatile("createpolicy.fractional.L2::evict_first.b64 %0, 1.0;\n"
                 : "=l"(pol));
    return pol;
}
__device__ __forceinline__ void cp_async16_pol(void* smem_dst, const void* gmem_src,
                                               uint64_t pol) {
    unsigned saddr = (unsigned)__cvta_generic_to_shared(smem_dst);
    asm volatile("cp.async.cg.shared.global.L2::cache_hint [%0], [%1], 16, %2;\n"
                 :: "r"(saddr), "l"(gmem_src), "l"(pol));
}
__device__ __forceinline__ void cp_commit() {
    asm volatile("cp.async.commit_group;\n" ::: "memory");
}
template <int Npend>
__device__ __forceinline__ void cp_wait() {
    asm volatile("cp.async.wait_group %0;\n" :: "n"(Npend) : "memory");
}

__global__ __launch_bounds__(CTA_CH, 1)
void cw_recurrence_kernel(const float* __restrict__ E,
                          const float* __restrict__ r,
                          const float* __restrict__ tau_nu,
                          const float* __restrict__ M,
                          const float* __restrict__ sigma,
                          const float* __restrict__ th,
                          float* __restrict__ out)
{
    // [stage][warp][256 float4]  (each warp owns its own 4KB tile slice)
    __shared__ float4 sbuf[STAGES][WARPS][F4_PER_WARP_TILE];

    const int tid   = threadIdx.x;
    const int w     = tid >> 5;
    const int lane  = tid & 31;

    const int nCtaPerCh = (CW_B * CW_N) / CTA_CH;        // 128
    const int chunk = blockIdx.x / nCtaPerCh;            // 0..CHUNKS-1
    const int cta   = blockIdx.x % nCtaPerCh;

    const int ch0 = cta * CTA_CH;                        // first channel of CTA
    const int ch  = ch0 + tid;
    const int b   = ch >> 10;                            // batch (uniform per CTA)
    const int n   = ch & (CW_N - 1);
    const int nw0 = (ch0 & (CW_N - 1)) + 32 * w;         // first channel of warp

    // Per-channel constants (off the recurrence chain)
    const float rr   = r[n];
    const float coef = CW_DT / tau_nu[n];
    const float a    = 1.0f - coef;
    const float cM   = coef * M[n];
    const float s    = sigma[n];
    const float sig2 = s * s;
    const float thv  = th[n];

    const int warm    = (chunk == 0) ? 0 : WARM;
    const int t0      = chunk * CW_L - warm;             // first integrated step
    const int nsteps  = CW_L + warm;
    const int NT      = nsteps / K_TILE;                 // tiles this chunk
    const int warm_nt = warm / K_TILE;                   // tiles with no store

    const float* eWarp = E   + ((size_t)b * CW_T + t0) * CW_N + nw0;
    float*       oPtr  = out + ((size_t)b * CW_T + t0) * CW_N + n;

    const uint64_t pol_last  = mk_evict_last_policy();
    const uint64_t pol_first = mk_evict_first_policy();

    // per-warp async tile load: rows [tile*K, tile*K+K), channels [nw0, nw0+32)
    auto load_tile = [&](int tile, int stage) {
        const float* src = eWarp + (size_t)tile * K_TILE * CW_N;
        // Absolute time of this tile's first row; pin the doubly-read seam
        // regions [cL-96, cL) for c=1..3 (uniform per tile: 96,1024 % 32 == 0)
        const int t_abs = t0 + tile * K_TILE;
        const bool pin  = ((t_abs & (CW_L - 1)) >= CW_L - WARM) &&
                          (t_abs < CW_T - CW_L);
        const uint64_t pol = pin ? pol_last : pol_first;
        #pragma unroll
        for (int p = 0; p < PASSES; ++p) {
            int idx = p * 32 + lane;         // 0..255
            int j   = idx >> 3;              // time row (8 float4 per row)
            int c4  = idx & 7;
            cp_async16_pol(&sbuf[stage][w][j * 8 + c4],
                           src + (size_t)j * CW_N + (c4 << 2), pol);
        }
    };

    #pragma unroll
    for (int s0 = 0; s0 < STAGES; ++s0) {
        load_tile(s0, s0);
        cp_commit();
    }

    float nu = 0.0f;

    for (int tile = 0; tile < NT; ++tile) {
        cp_wait<STAGES - 1>();               // this tile's group complete (per-thread)

        const int stage = tile % STAGES;
        const float* sf = (const float*)&sbuf[stage][w][0];
        float* op = oPtr + (size_t)tile * K_TILE * CW_N;
        const bool do_store = (tile >= warm_nt);

        #pragma unroll
        for (int j = 0; j < K_TILE; ++j) {
            const float e = sf[j * 32 + lane];

            // critical path: u -> d -> rcp -> fma  (~28 cyc)
            const float u  = fmaf(-rr, nu, e);       // e - r*nu
            const float d  = fmaf(u, u, sig2);       // u^2 + sigma^2
            float ri;
            asm("rcp.approx.f32 %0, %1;" : "=f"(ri) : "f"(d));

            // off-chain, overlaps the rcp
            const float an = a * nu;
            const float rl = fmaxf(u + thv, 0.0f);
            const float p  = cM * u * rl;

            nu = fmaf(p, ri, an);
            if (do_store)
                __stcs(&op[(size_t)j * CW_N], nu);   // evict-first store
        }

        const int nxt = tile + STAGES;
        if (nxt < NT) load_tile(nxt, stage); // warp-private: no __syncthreads needed
        cp_commit();                         // keep group count consistent
    }
}

extern "C" void kernel_launch(void* const* d_in, const int* in_sizes, int n_in,
                              void* d_out, int out_size)
{
    const float* E      = (const float*)d_in[0];
    const float* r      = (const float*)d_in[1];
    const float* tau_nu = (const float*)d_in[2];
    const float* M      = (const float*)d_in[3];
    const float* sigma  = (const float*)d_in[4];
    const float* th     = (const float*)d_in[5];
    float* out = (float*)d_out;

    // 128 CTAs per chunk x 4 chunks = 512 CTAs, 64 threads each
    cw_recurrence_kernel<<<((CW_B * CW_N) / CTA_CH) * CHUNKS, CTA_CH>>>(
        E, r, tau_nu, M, sigma, th, out);
}